// round 1
// baseline (speedup 1.0000x reference)
#include <cuda_runtime.h>
#include <cstdint>

#define NSLOTS 8
#define NKEYS  8192
#define KDIM   256
#define VDIM   512
#define NQ     4096
#define IN_DIM 512
#define TOPK   32

// scratch (device globals are the sanctioned alloc-free scratch)
__device__ float g_q[NQ * KDIM];        // 4 MB
__device__ float g_resid[NQ * VDIM];    // 8 MB
__device__ float g_invn[NSLOTS * NKEYS];

// ---------------------------------------------------------------------------
// Generic fp32 GEMM (NT): C[M][N] = sum_k A[M][K][m,k] * B[N][K][n,k] + bias[n]
// BM=64, BN=64, BK=16, TM=8, TN=4, 128 threads. Requires M%64==N%64==K%16==0.
// ---------------------------------------------------------------------------
__global__ __launch_bounds__(128) void gemm_nt_bias(
    const float* __restrict__ A, const float* __restrict__ B,
    const float* __restrict__ bias, float* __restrict__ C,
    int M, int N, int K)
{
    __shared__ float As[16][68];
    __shared__ float Bs[16][68];
    const int tid = threadIdx.x;
    const int tx = tid & 15;        // 0..15 (n)
    const int ty = tid >> 4;        // 0..7  (m)
    const int m0 = blockIdx.y * 64, n0 = blockIdx.x * 64;

    float acc[8][4];
#pragma unroll
    for (int i = 0; i < 8; i++)
#pragma unroll
        for (int j = 0; j < 4; j++) acc[i][j] = 0.f;

    for (int k0 = 0; k0 < K; k0 += 16) {
        __syncthreads();
#pragma unroll
        for (int i = 0; i < 2; i++) {
            int f = tid + i * 128;
            int r = f >> 2, q4 = (f & 3) << 2;
            float4 va = *(const float4*)(A + (size_t)(m0 + r) * K + k0 + q4);
            As[q4 + 0][r] = va.x; As[q4 + 1][r] = va.y;
            As[q4 + 2][r] = va.z; As[q4 + 3][r] = va.w;
            float4 vb = *(const float4*)(B + (size_t)(n0 + r) * K + k0 + q4);
            Bs[q4 + 0][r] = vb.x; Bs[q4 + 1][r] = vb.y;
            Bs[q4 + 2][r] = vb.z; Bs[q4 + 3][r] = vb.w;
        }
        __syncthreads();
#pragma unroll
        for (int k = 0; k < 16; k++) {
            float4 a0 = *(const float4*)&As[k][ty * 8];
            float4 a1 = *(const float4*)&As[k][ty * 8 + 4];
            float4 b  = *(const float4*)&Bs[k][tx * 4];
            float av[8] = {a0.x, a0.y, a0.z, a0.w, a1.x, a1.y, a1.z, a1.w};
            float bv[4] = {b.x, b.y, b.z, b.w};
#pragma unroll
            for (int i = 0; i < 8; i++)
#pragma unroll
                for (int j = 0; j < 4; j++) acc[i][j] += av[i] * bv[j];
        }
    }
    const int n = n0 + tx * 4;
    float4 bb = *(const float4*)(bias + n);
#pragma unroll
    for (int i = 0; i < 8; i++) {
        float4 o = make_float4(acc[i][0] + bb.x, acc[i][1] + bb.y,
                               acc[i][2] + bb.z, acc[i][3] + bb.w);
        *(float4*)(C + (size_t)(m0 + ty * 8 + i) * N + n) = o;
    }
}

// ---------------------------------------------------------------------------
// inverse key norms: one warp per key
// ---------------------------------------------------------------------------
__global__ __launch_bounds__(256) void key_norms(
    const float* __restrict__ keys, float* __restrict__ invn)
{
    const int lane = threadIdx.x & 31;
    const int key = blockIdx.x * 8 + (threadIdx.x >> 5);
    const float4* kp = (const float4*)(keys + (size_t)key * KDIM);
    float4 v0 = kp[lane], v1 = kp[lane + 32];
    float s = v0.x * v0.x + v0.y * v0.y + v0.z * v0.z + v0.w * v0.w
            + v1.x * v1.x + v1.y * v1.y + v1.z * v1.z + v1.w * v1.w;
#pragma unroll
    for (int o = 16; o; o >>= 1) s += __shfl_xor_sync(0xffffffffu, s, o);
    if (lane == 0) invn[key] = rsqrtf(s);
}

// ---------------------------------------------------------------------------
// fused: tf32-mma scores + running top-32 heap + softmax + value gather
// grid (NQ/128, NSLOTS), 256 threads
// ---------------------------------------------------------------------------
__device__ __forceinline__ unsigned f2tf32(float x) {
    unsigned u;
    asm("cvt.rna.tf32.f32 %0, %1;" : "=r"(u) : "f"(x));
    return u;
}

__device__ __forceinline__ void mma_tf32(float c[4], const unsigned a[4],
                                         unsigned b0, unsigned b1) {
    asm volatile(
        "mma.sync.aligned.m16n8k8.row.col.f32.tf32.tf32.f32 "
        "{%0,%1,%2,%3}, {%4,%5,%6,%7}, {%8,%9}, {%0,%1,%2,%3};\n"
        : "+f"(c[0]), "+f"(c[1]), "+f"(c[2]), "+f"(c[3])
        : "r"(a[0]), "r"(a[1]), "r"(a[2]), "r"(a[3]), "r"(b0), "r"(b1));
}

#define SQ_LD 260   // 128 x 260 fp32(tf32) q tile     (bank-conflict-free frag loads)
#define SK_LD 36    // 64 x 36 key chunk
#define SS_LD 66    // 128 x 66 score staging
#define HP_LD 33    // 128 x 33 heap stride
#define FUSED_SMEM_FLOATS (128*SQ_LD + 64*SK_LD + 128*SS_LD + 64 + 128*HP_LD + 128*HP_LD)

__global__ __launch_bounds__(256, 1) void fused_slot(
    const float* __restrict__ keys, const float* __restrict__ values,
    float* __restrict__ out)
{
    extern __shared__ float smem[];
    float* sQ   = smem;
    float* sK   = sQ + 128 * SQ_LD;
    float* sS   = sK + 64 * SK_LD;
    float* sInv = sS + 128 * SS_LD;
    float* hS   = sInv + 64;
    int*   hI   = (int*)(hS + 128 * HP_LD);

    const int tid  = threadIdx.x;
    const int lane = tid & 31, wid = tid >> 5;
    const int warp_m = wid >> 1;   // 0..3 -> 32 query rows each
    const int warp_n = wid & 1;    // 0..1 -> 32 key cols each
    const int g = lane >> 2, tig = lane & 3;
    const int slot = blockIdx.y;
    const int q0 = blockIdx.x * 128;

    // ---- load q tile (tf32-rounded) ----
    const float4* qg4 = (const float4*)(g_q + (size_t)q0 * KDIM);
#pragma unroll
    for (int i = 0; i < 32; i++) {
        int f = tid + i * 256;              // float4 index, 0..8191
        int row = f >> 6, c4 = (f & 63) << 2;
        float4 v = qg4[f];
        uint4 u = make_uint4(f2tf32(v.x), f2tf32(v.y), f2tf32(v.z), f2tf32(v.w));
        *(uint4*)&sQ[row * SQ_LD + c4] = u;
    }
    // ---- init heaps (always-full min-heaps seeded at -inf-ish) ----
    for (int i = tid; i < 128 * HP_LD; i += 256) { hS[i] = -3.0e38f; hI[i] = 0; }

    const float* keybase = keys + (size_t)slot * NKEYS * KDIM;

    for (int kc = 0; kc < NKEYS / 64; kc++) {
        const int key0 = kc * 64;
        float c[2][4][4];
#pragma unroll
        for (int mm = 0; mm < 2; mm++)
#pragma unroll
            for (int nn = 0; nn < 4; nn++)
#pragma unroll
                for (int r = 0; r < 4; r++) c[mm][nn][r] = 0.f;

        for (int kk = 0; kk < KDIM; kk += 32) {
            __syncthreads();   // sK reuse + (chunk start) prev topk done
#pragma unroll
            for (int i = 0; i < 2; i++) {
                int f = tid + i * 256;              // float4 idx, 0..511
                int key = f >> 3, c4 = (f & 7) << 2;
                float4 v = *(const float4*)(keybase +
                            (size_t)(key0 + key) * KDIM + kk + c4);
                uint4 u = make_uint4(f2tf32(v.x), f2tf32(v.y),
                                     f2tf32(v.z), f2tf32(v.w));
                *(uint4*)&sK[key * SK_LD + c4] = u;
            }
            if (kk == 0 && tid < 64)
                sInv[tid] = g_invn[slot * NKEYS + key0 + tid];
            __syncthreads();

#pragma unroll
            for (int ks = 0; ks < 4; ks++) {
                const int kb = ks * 8;
                unsigned a[2][4];
#pragma unroll
                for (int mm = 0; mm < 2; mm++) {
                    const float* qp = sQ + (warp_m * 32 + mm * 16) * SQ_LD
                                         + kk + kb + tig;
                    a[mm][0] = __float_as_uint(qp[g * SQ_LD]);
                    a[mm][1] = __float_as_uint(qp[(g + 8) * SQ_LD]);
                    a[mm][2] = __float_as_uint(qp[g * SQ_LD + 4]);
                    a[mm][3] = __float_as_uint(qp[(g + 8) * SQ_LD + 4]);
                }
#pragma unroll
                for (int nn = 0; nn < 4; nn++) {
                    const float* kp = sK + (warp_n * 32 + nn * 8 + g) * SK_LD
                                         + kb + tig;
                    unsigned b0 = __float_as_uint(kp[0]);
                    unsigned b1 = __float_as_uint(kp[4]);
                    mma_tf32(c[0][nn], a[0], b0, b1);
                    mma_tf32(c[1][nn], a[1], b0, b1);
                }
            }
        }
        // ---- scale by inv-norm, stage scores ----
#pragma unroll
        for (int mm = 0; mm < 2; mm++) {
            int row0 = warp_m * 32 + mm * 16 + g;
#pragma unroll
            for (int nn = 0; nn < 4; nn++) {
                int col = warp_n * 32 + nn * 8 + 2 * tig;
                float i0 = sInv[col], i1 = sInv[col + 1];
                *(float2*)&sS[row0 * SS_LD + col] =
                    make_float2(c[mm][nn][0] * i0, c[mm][nn][1] * i1);
                *(float2*)&sS[(row0 + 8) * SS_LD + col] =
                    make_float2(c[mm][nn][2] * i0, c[mm][nn][3] * i1);
            }
        }
        __syncthreads();
        // ---- top-k update: one thread per query ----
        if (tid < 128) {
            float* hs = hS + tid * HP_LD;
            int*   hi = hI + tid * HP_LD;
            const float* srow = sS + tid * SS_LD;
#pragma unroll 4
            for (int j = 0; j < 64; j++) {
                float s = srow[j];
                if (s > hs[0]) {
                    int p = 0;
                    while (true) {
                        int cl = 2 * p + 1;
                        if (cl >= TOPK) break;
                        int cr = cl + 1;
                        if (cr < TOPK && hs[cr] < hs[cl]) cl = cr;
                        if (hs[cl] >= s) break;
                        hs[p] = hs[cl]; hi[p] = hi[cl]; p = cl;
                    }
                    hs[p] = s; hi[p] = key0 + j;
                }
            }
        }
        // leading sync of next chunk protects sS/sK
    }
    __syncthreads();

    // ---- softmax over top-32 + weighted value gather + residual ----
    const float* vbase = values + (size_t)slot * NKEYS * VDIM;
    for (int t = 0; t < 16; t++) {
        const int q = wid * 16 + t;
        const int qg_ = q0 + q;
        float s = hS[q * HP_LD + lane];
        int  ki = hI[q * HP_LD + lane];
        float m = s;
#pragma unroll
        for (int o = 16; o; o >>= 1)
            m = fmaxf(m, __shfl_xor_sync(0xffffffffu, m, o));
        float e = __expf(s - m);
        float sum = e;
#pragma unroll
        for (int o = 16; o; o >>= 1) sum += __shfl_xor_sync(0xffffffffu, sum, o);
        float w = e / sum;

        float4 acc[4];
#pragma unroll
        for (int j = 0; j < 4; j++) acc[j] = make_float4(0.f, 0.f, 0.f, 0.f);
#pragma unroll 4
        for (int k = 0; k < TOPK; k++) {
            float wk = __shfl_sync(0xffffffffu, w, k);
            int   ik = __shfl_sync(0xffffffffu, ki, k);
            const float4* vr = (const float4*)(vbase + (size_t)ik * VDIM);
#pragma unroll
            for (int j = 0; j < 4; j++) {
                float4 v = vr[lane + j * 32];
                acc[j].x += wk * v.x; acc[j].y += wk * v.y;
                acc[j].z += wk * v.z; acc[j].w += wk * v.w;
            }
        }
        const float4* rr = (const float4*)(g_resid + (size_t)qg_ * VDIM);
        float4* op = (float4*)(out + ((size_t)qg_ * NSLOTS + slot) * VDIM);
#pragma unroll
        for (int j = 0; j < 4; j++) {
            float4 r = rr[lane + j * 32];
            op[lane + j * 32] = make_float4(acc[j].x + r.x, acc[j].y + r.y,
                                            acc[j].z + r.z, acc[j].w + r.w);
        }
    }
}

// ---------------------------------------------------------------------------
extern "C" void kernel_launch(void* const* d_in, const int* in_sizes, int n_in,
                              void* d_out, int out_size)
{
    const float* x      = (const float*)d_in[0];
    const float* keys   = (const float*)d_in[1];
    const float* values = (const float*)d_in[2];
    const float* wq     = (const float*)d_in[3];
    const float* bq     = (const float*)d_in[4];
    const float* wr     = (const float*)d_in[5];
    const float* br     = (const float*)d_in[6];
    float* out = (float*)d_out;

    float *qp, *rp, *np;
    cudaGetSymbolAddress((void**)&qp, g_q);
    cudaGetSymbolAddress((void**)&rp, g_resid);
    cudaGetSymbolAddress((void**)&np, g_invn);

    // q = x @ wq^T + bq   (fp32, exact)
    gemm_nt_bias<<<dim3(KDIM / 64, NQ / 64), 128>>>(x, wq, bq, qp, NQ, KDIM, IN_DIM);
    // key inverse norms (independent of q)
    key_norms<<<NSLOTS * NKEYS / 8, 256>>>(keys, np);
    // residual = q @ wr^T + br  (fp32, exact)
    gemm_nt_bias<<<dim3(VDIM / 64, NQ / 64), 128>>>(qp, wr, br, rp, NQ, VDIM, KDIM);

    const int smem_bytes = FUSED_SMEM_FLOATS * 4;
    cudaFuncSetAttribute(fused_slot,
                         cudaFuncAttributeMaxDynamicSharedMemorySize, smem_bytes);
    fused_slot<<<dim3(NQ / 128, NSLOTS), 256, smem_bytes>>>(keys, values, out);
}

// round 2
// speedup vs baseline: 1.1374x; 1.1374x over previous
#include <cuda_runtime.h>
#include <cstdint>

#define NSLOTS 8
#define NKEYS  8192
#define KDIM   256
#define VDIM   512
#define NQ     4096
#define IN_DIM 512
#define TOPK   32

// device-global scratch (sanctioned alloc-free scratch)
__device__ float g_q[NQ * KDIM];                    // 4 MB
__device__ float g_resid[NQ * VDIM];                // 8 MB
__device__ float g_keysn[NSLOTS * NKEYS * KDIM];    // 64 MB normalized tf32-rounded keys

// ---------------------------------------------------------------------------
// fp32 GEMM (NT): C = A·Bᵀ + bias. BM=64,BN=64,BK=16,TM=8,TN=4, 128 thr.
// ---------------------------------------------------------------------------
__global__ __launch_bounds__(128) void gemm_nt_bias(
    const float* __restrict__ A, const float* __restrict__ B,
    const float* __restrict__ bias, float* __restrict__ C,
    int M, int N, int K)
{
    __shared__ float As[16][68];
    __shared__ float Bs[16][68];
    const int tid = threadIdx.x;
    const int tx = tid & 15, ty = tid >> 4;
    const int m0 = blockIdx.y * 64, n0 = blockIdx.x * 64;

    float acc[8][4];
#pragma unroll
    for (int i = 0; i < 8; i++)
#pragma unroll
        for (int j = 0; j < 4; j++) acc[i][j] = 0.f;

    for (int k0 = 0; k0 < K; k0 += 16) {
        __syncthreads();
#pragma unroll
        for (int i = 0; i < 2; i++) {
            int f = tid + i * 128;
            int r = f >> 2, q4 = (f & 3) << 2;
            float4 va = *(const float4*)(A + (size_t)(m0 + r) * K + k0 + q4);
            As[q4 + 0][r] = va.x; As[q4 + 1][r] = va.y;
            As[q4 + 2][r] = va.z; As[q4 + 3][r] = va.w;
            float4 vb = *(const float4*)(B + (size_t)(n0 + r) * K + k0 + q4);
            Bs[q4 + 0][r] = vb.x; Bs[q4 + 1][r] = vb.y;
            Bs[q4 + 2][r] = vb.z; Bs[q4 + 3][r] = vb.w;
        }
        __syncthreads();
#pragma unroll
        for (int k = 0; k < 16; k++) {
            float4 a0 = *(const float4*)&As[k][ty * 8];
            float4 a1 = *(const float4*)&As[k][ty * 8 + 4];
            float4 b  = *(const float4*)&Bs[k][tx * 4];
            float av[8] = {a0.x, a0.y, a0.z, a0.w, a1.x, a1.y, a1.z, a1.w};
            float bv[4] = {b.x, b.y, b.z, b.w};
#pragma unroll
            for (int i = 0; i < 8; i++)
#pragma unroll
                for (int j = 0; j < 4; j++) acc[i][j] += av[i] * bv[j];
        }
    }
    const int n = n0 + tx * 4;
    float4 bb = *(const float4*)(bias + n);
#pragma unroll
    for (int i = 0; i < 8; i++) {
        float4 o = make_float4(acc[i][0] + bb.x, acc[i][1] + bb.y,
                               acc[i][2] + bb.z, acc[i][3] + bb.w);
        *(float4*)(C + (size_t)(m0 + ty * 8 + i) * N + n) = o;
    }
}

// ---------------------------------------------------------------------------
__device__ __forceinline__ unsigned f2tf32(float x) {
    unsigned u;
    asm("cvt.rna.tf32.f32 %0, %1;" : "=r"(u) : "f"(x));
    return u;
}
__device__ __forceinline__ float tf32r(float x) { return __uint_as_float(f2tf32(x)); }

// keys -> normalized, tf32-rounded, stored fp32. one warp per key.
__global__ __launch_bounds__(256) void normalize_keys(
    const float* __restrict__ keys, float* __restrict__ kn)
{
    const int lane = threadIdx.x & 31;
    const int key = blockIdx.x * 8 + (threadIdx.x >> 5);
    const float4* kp = (const float4*)(keys + (size_t)key * KDIM);
    float4 v0 = kp[lane], v1 = kp[lane + 32];
    float s = v0.x * v0.x + v0.y * v0.y + v0.z * v0.z + v0.w * v0.w
            + v1.x * v1.x + v1.y * v1.y + v1.z * v1.z + v1.w * v1.w;
#pragma unroll
    for (int o = 16; o; o >>= 1) s += __shfl_xor_sync(0xffffffffu, s, o);
    float inv = rsqrtf(s);
    float4* op = (float4*)(kn + (size_t)key * KDIM);
    float4 o0 = make_float4(tf32r(v0.x * inv), tf32r(v0.y * inv),
                            tf32r(v0.z * inv), tf32r(v0.w * inv));
    float4 o1 = make_float4(tf32r(v1.x * inv), tf32r(v1.y * inv),
                            tf32r(v1.z * inv), tf32r(v1.w * inv));
    op[lane] = o0; op[lane + 32] = o1;
}

// ---------------------------------------------------------------------------
__device__ __forceinline__ void mma_tf32(float c[4], const unsigned a[4],
                                         unsigned b0, unsigned b1) {
    asm volatile(
        "mma.sync.aligned.m16n8k8.row.col.f32.tf32.tf32.f32 "
        "{%0,%1,%2,%3}, {%4,%5,%6,%7}, {%8,%9}, {%0,%1,%2,%3};\n"
        : "+f"(c[0]), "+f"(c[1]), "+f"(c[2]), "+f"(c[3])
        : "r"(a[0]), "r"(a[1]), "r"(a[2]), "r"(a[3]), "r"(b0), "r"(b1));
}

#define SQ_LD 260          // 128 rows (q, tf32)
#define SK_LD 20           // 128 keys x 16 dims per stage
#define SS_LD 65           // 128 x 64 score staging (conflict-free topk reads)
#define NCHUNK (NKEYS / 128)      // 64
#define NSTAGE (NCHUNK * 16)      // 1024 (16-dim stages)
// floats: 128*260 + 3*128*20 + 128*65 + 128*33 + (128*34)/2 = 55680 -> 222720 B
#define FUSED_SMEM_BYTES (55680 * 4)

__device__ __forceinline__ void issue_stage(
    float* sK, const float* __restrict__ keybase, int tid, int s)
{
    if (s < NSTAGE) {
        const float* gb = keybase + (size_t)((s >> 4) << 7) * KDIM + ((s & 15) << 4);
        float* sb = sK + (s % 3) * (128 * SK_LD);
#pragma unroll
        for (int i = 0; i < 2; i++) {
            int f = tid + i * 256;
            int key = f >> 2, c4 = (f & 3) << 2;
            unsigned saddr = (unsigned)__cvta_generic_to_shared(sb + key * SK_LD + c4);
            const float* ga = gb + (size_t)key * KDIM + c4;
            asm volatile("cp.async.cg.shared.global [%0], [%1], 16;\n"
                         :: "r"(saddr), "l"(ga));
        }
    }
    asm volatile("cp.async.commit_group;\n");   // empty group at tail keeps counting
}

__global__ __launch_bounds__(256, 1) void fused_slot(
    const float* __restrict__ keysn, const float* __restrict__ values,
    float* __restrict__ out)
{
    extern __shared__ float smem[];
    float* sQ = smem;
    float* sK = sQ + 128 * SQ_LD;
    float* sS = sK + 3 * 128 * SK_LD;
    float* hS = sS + 128 * SS_LD;
    unsigned short* hI = (unsigned short*)(hS + 128 * 33);

    const int tid  = threadIdx.x;
    const int lane = tid & 31, wid = tid >> 5;
    const int warp_m = wid >> 2;   // 0..1 -> 64 query rows
    const int warp_n = wid & 3;    // 0..3 -> 32 key cols of the 128-chunk
    const int g = lane >> 2, tig = lane & 3;
    const int slot = blockIdx.y;
    const int q0 = blockIdx.x * 128;
    const float* keybase = keysn + (size_t)slot * NKEYS * KDIM;

    // kick the pipeline before anything else
    issue_stage(sK, keybase, tid, 0);
    issue_stage(sK, keybase, tid, 1);

    // q tile (tf32-rounded), overlapped with first key copies
    const float4* qg4 = (const float4*)(g_q + (size_t)q0 * KDIM);
#pragma unroll
    for (int i = 0; i < 32; i++) {
        int f = tid + i * 256;
        int row = f >> 6, c4 = (f & 63) << 2;
        float4 v = qg4[f];
        uint4 u = make_uint4(f2tf32(v.x), f2tf32(v.y), f2tf32(v.z), f2tf32(v.w));
        *(uint4*)&sQ[row * SQ_LD + c4] = u;
    }
    // heaps
    for (int i = tid; i < 128 * 33; i += 256) hS[i] = -3.0e38f;
    for (int i = tid; i < 128 * 34; i += 256) hI[i] = 0;

    float c[4][4][4];
#pragma unroll
    for (int mm = 0; mm < 4; mm++)
#pragma unroll
        for (int nn = 0; nn < 4; nn++)
#pragma unroll
            for (int r = 0; r < 4; r++) c[mm][nn][r] = 0.f;

    for (int s = 0; s < NSTAGE; s++) {
        asm volatile("cp.async.wait_group 1;\n" ::: "memory");
        __syncthreads();                 // stage s visible to all; buf (s-1)%3 free
        issue_stage(sK, keybase, tid, s + 2);

        const float* kbuf = sK + (s % 3) * (128 * SK_LD);
        const int kk = (s & 15) << 4;
#pragma unroll
        for (int ks = 0; ks < 2; ks++) {
            unsigned a[4][4];
            const float* qp = sQ + (warp_m * 64) * SQ_LD + kk + ks * 8 + tig;
#pragma unroll
            for (int mm = 0; mm < 4; mm++) {
                const float* qpp = qp + mm * 16 * SQ_LD;
                a[mm][0] = __float_as_uint(qpp[g * SQ_LD]);
                a[mm][1] = __float_as_uint(qpp[(g + 8) * SQ_LD]);
                a[mm][2] = __float_as_uint(qpp[g * SQ_LD + 4]);
                a[mm][3] = __float_as_uint(qpp[(g + 8) * SQ_LD + 4]);
            }
#pragma unroll
            for (int nn = 0; nn < 4; nn++) {
                const float* kp = kbuf + (warp_n * 32 + nn * 8 + g) * SK_LD
                                       + ks * 8 + tig;
                unsigned b0 = __float_as_uint(kp[0]);
                unsigned b1 = __float_as_uint(kp[4]);
#pragma unroll
                for (int mm = 0; mm < 4; mm++) mma_tf32(c[mm][nn], a[mm], b0, b1);
            }
        }

        if ((s & 15) == 15) {            // chunk of 128 keys complete
            const int key0 = (s >> 4) << 7;
#pragma unroll
            for (int half = 0; half < 2; half++) {
                // stage scores: half 0 = warp_n {0,1} -> cols 0..63, half 1 = {2,3}
                if ((warp_n >> 1) == half) {
                    const int cb = (warp_n & 1) * 32;
#pragma unroll
                    for (int mm = 0; mm < 4; mm++) {
                        int r0 = warp_m * 64 + mm * 16 + g;
#pragma unroll
                        for (int nn = 0; nn < 4; nn++) {
                            int col = cb + nn * 8 + 2 * tig;
                            sS[r0 * SS_LD + col]           = c[mm][nn][0];
                            sS[r0 * SS_LD + col + 1]       = c[mm][nn][1];
                            sS[(r0 + 8) * SS_LD + col]     = c[mm][nn][2];
                            sS[(r0 + 8) * SS_LD + col + 1] = c[mm][nn][3];
                        }
                    }
                }
                __syncthreads();
                if (tid < 128) {          // one thread per query: top-k update
                    float* hs = hS + tid * 33;
                    unsigned short* hi = hI + tid * 34;
                    const float* srow = sS + tid * SS_LD;
                    float hmin = hs[0];
                    const int kb = key0 + half * 64;
#pragma unroll 4
                    for (int j = 0; j < 64; j++) {
                        float v = srow[j];
                        if (v > hmin) {
                            int p = 0;
                            while (true) {
                                int cl = 2 * p + 1;
                                if (cl >= TOPK) break;
                                int cr = cl + 1;
                                if (cr < TOPK && hs[cr] < hs[cl]) cl = cr;
                                if (hs[cl] >= v) break;
                                hs[p] = hs[cl]; hi[p] = hi[cl]; p = cl;
                            }
                            hs[p] = v; hi[p] = (unsigned short)(kb + j);
                            hmin = hs[0];
                        }
                    }
                }
                if (half == 0) __syncthreads();
            }
            // reset accumulators for next chunk
#pragma unroll
            for (int mm = 0; mm < 4; mm++)
#pragma unroll
                for (int nn = 0; nn < 4; nn++)
#pragma unroll
                    for (int r = 0; r < 4; r++) c[mm][nn][r] = 0.f;
        }
    }
    __syncthreads();

    // softmax over top-32 + weighted value gather + residual
    const float* vbase = values + (size_t)slot * NKEYS * VDIM;
    for (int t = 0; t < 16; t++) {
        const int q = wid * 16 + t;
        const int qg_ = q0 + q;
        float s = hS[q * 33 + lane];
        int  ki = hI[q * 34 + lane];
        float m = s;
#pragma unroll
        for (int o = 16; o; o >>= 1)
            m = fmaxf(m, __shfl_xor_sync(0xffffffffu, m, o));
        float e = __expf(s - m);
        float sum = e;
#pragma unroll
        for (int o = 16; o; o >>= 1) sum += __shfl_xor_sync(0xffffffffu, sum, o);
        float w = e / sum;

        float4 acc[4];
#pragma unroll
        for (int j = 0; j < 4; j++) acc[j] = make_float4(0.f, 0.f, 0.f, 0.f);
#pragma unroll 4
        for (int k = 0; k < TOPK; k++) {
            float wk = __shfl_sync(0xffffffffu, w, k);
            int   ik = __shfl_sync(0xffffffffu, ki, k);
            const float4* vr = (const float4*)(vbase + (size_t)ik * VDIM);
#pragma unroll
            for (int j = 0; j < 4; j++) {
                float4 v = vr[lane + j * 32];
                acc[j].x += wk * v.x; acc[j].y += wk * v.y;
                acc[j].z += wk * v.z; acc[j].w += wk * v.w;
            }
        }
        const float4* rr = (const float4*)(g_resid + (size_t)qg_ * VDIM);
        float4* op = (float4*)(out + ((size_t)qg_ * NSLOTS + slot) * VDIM);
#pragma unroll
        for (int j = 0; j < 4; j++) {
            float4 r = rr[lane + j * 32];
            op[lane + j * 32] = make_float4(acc[j].x + r.x, acc[j].y + r.y,
                                            acc[j].z + r.z, acc[j].w + r.w);
        }
    }
}

// ---------------------------------------------------------------------------
extern "C" void kernel_launch(void* const* d_in, const int* in_sizes, int n_in,
                              void* d_out, int out_size)
{
    const float* x      = (const float*)d_in[0];
    const float* keys   = (const float*)d_in[1];
    const float* values = (const float*)d_in[2];
    const float* wq     = (const float*)d_in[3];
    const float* bq     = (const float*)d_in[4];
    const float* wr     = (const float*)d_in[5];
    const float* br     = (const float*)d_in[6];
    float* out = (float*)d_out;

    float *qp, *rp, *kp;
    cudaGetSymbolAddress((void**)&qp, g_q);
    cudaGetSymbolAddress((void**)&rp, g_resid);
    cudaGetSymbolAddress((void**)&kp, g_keysn);

    // normalized tf32 keys (independent of q)
    normalize_keys<<<NSLOTS * NKEYS / 8, 256>>>(keys, kp);
    // q = x @ wq^T + bq (fp32 exact)
    gemm_nt_bias<<<dim3(KDIM / 64, NQ / 64), 128>>>(x, wq, bq, qp, NQ, KDIM, IN_DIM);
    // residual = q @ wr^T + br (fp32 exact)
    gemm_nt_bias<<<dim3(VDIM / 64, NQ / 64), 128>>>(qp, wr, br, rp, NQ, VDIM, KDIM);

    cudaFuncSetAttribute(fused_slot,
                         cudaFuncAttributeMaxDynamicSharedMemorySize,
                         FUSED_SMEM_BYTES);
    fused_slot<<<dim3(NQ / 128, NSLOTS), 256, FUSED_SMEM_BYTES>>>(kp, values, out);
}

// round 3
// speedup vs baseline: 1.2203x; 1.0730x over previous
#include <cuda_runtime.h>
#include <cstdint>

#define NSLOTS 8
#define NKEYS  8192
#define KDIM   256
#define VDIM   512
#define NQ     4096
#define IN_DIM 512
#define TOPK   32

__device__ float g_q[NQ * KDIM];                    // 4 MB
__device__ float g_resid[NQ * VDIM];                // 8 MB
__device__ float g_keysn[NSLOTS * NKEYS * KDIM];    // 64 MB normalized tf32 keys

// ---------------------------------------------------------------------------
// fp32 GEMM (NT): C = A·Bᵀ + bias. BM=64,BN=64,BK=16,TM=8,TN=4, 128 thr.
// ---------------------------------------------------------------------------
__global__ __launch_bounds__(128) void gemm_nt_bias(
    const float* __restrict__ A, const float* __restrict__ B,
    const float* __restrict__ bias, float* __restrict__ C,
    int M, int N, int K)
{
    __shared__ float As[16][68];
    __shared__ float Bs[16][68];
    const int tid = threadIdx.x;
    const int tx = tid & 15, ty = tid >> 4;
    const int m0 = blockIdx.y * 64, n0 = blockIdx.x * 64;

    float acc[8][4];
#pragma unroll
    for (int i = 0; i < 8; i++)
#pragma unroll
        for (int j = 0; j < 4; j++) acc[i][j] = 0.f;

    for (int k0 = 0; k0 < K; k0 += 16) {
        __syncthreads();
#pragma unroll
        for (int i = 0; i < 2; i++) {
            int f = tid + i * 128;
            int r = f >> 2, q4 = (f & 3) << 2;
            float4 va = *(const float4*)(A + (size_t)(m0 + r) * K + k0 + q4);
            As[q4 + 0][r] = va.x; As[q4 + 1][r] = va.y;
            As[q4 + 2][r] = va.z; As[q4 + 3][r] = va.w;
            float4 vb = *(const float4*)(B + (size_t)(n0 + r) * K + k0 + q4);
            Bs[q4 + 0][r] = vb.x; Bs[q4 + 1][r] = vb.y;
            Bs[q4 + 2][r] = vb.z; Bs[q4 + 3][r] = vb.w;
        }
        __syncthreads();
#pragma unroll
        for (int k = 0; k < 16; k++) {
            float4 a0 = *(const float4*)&As[k][ty * 8];
            float4 a1 = *(const float4*)&As[k][ty * 8 + 4];
            float4 b  = *(const float4*)&Bs[k][tx * 4];
            float av[8] = {a0.x, a0.y, a0.z, a0.w, a1.x, a1.y, a1.z, a1.w};
            float bv[4] = {b.x, b.y, b.z, b.w};
#pragma unroll
            for (int i = 0; i < 8; i++)
#pragma unroll
                for (int j = 0; j < 4; j++) acc[i][j] += av[i] * bv[j];
        }
    }
    const int n = n0 + tx * 4;
    float4 bb = *(const float4*)(bias + n);
#pragma unroll
    for (int i = 0; i < 8; i++) {
        float4 o = make_float4(acc[i][0] + bb.x, acc[i][1] + bb.y,
                               acc[i][2] + bb.z, acc[i][3] + bb.w);
        *(float4*)(C + (size_t)(m0 + ty * 8 + i) * N + n) = o;
    }
}

// ---------------------------------------------------------------------------
__device__ __forceinline__ unsigned f2tf32(float x) {
    unsigned u;
    asm("cvt.rna.tf32.f32 %0, %1;" : "=r"(u) : "f"(x));
    return u;
}
__device__ __forceinline__ float tf32r(float x) { return __uint_as_float(f2tf32(x)); }

// keys -> normalized, tf32-rounded. one warp per key.
__global__ __launch_bounds__(256) void normalize_keys(
    const float* __restrict__ keys, float* __restrict__ kn)
{
    const int lane = threadIdx.x & 31;
    const int key = blockIdx.x * 8 + (threadIdx.x >> 5);
    const float4* kp = (const float4*)(keys + (size_t)key * KDIM);
    float4 v0 = kp[lane], v1 = kp[lane + 32];
    float s = v0.x * v0.x + v0.y * v0.y + v0.z * v0.z + v0.w * v0.w
            + v1.x * v1.x + v1.y * v1.y + v1.z * v1.z + v1.w * v1.w;
#pragma unroll
    for (int o = 16; o; o >>= 1) s += __shfl_xor_sync(0xffffffffu, s, o);
    float inv = rsqrtf(s);
    float4* op = (float4*)(kn + (size_t)key * KDIM);
    op[lane]      = make_float4(tf32r(v0.x * inv), tf32r(v0.y * inv),
                                tf32r(v0.z * inv), tf32r(v0.w * inv));
    op[lane + 32] = make_float4(tf32r(v1.x * inv), tf32r(v1.y * inv),
                                tf32r(v1.z * inv), tf32r(v1.w * inv));
}

// ---------------------------------------------------------------------------
__device__ __forceinline__ void mma_tf32(float c[4], const unsigned a[4],
                                         unsigned b0, unsigned b1) {
    asm volatile(
        "mma.sync.aligned.m16n8k8.row.col.f32.tf32.tf32.f32 "
        "{%0,%1,%2,%3}, {%4,%5,%6,%7}, {%8,%9}, {%0,%1,%2,%3};\n"
        : "+f"(c[0]), "+f"(c[1]), "+f"(c[2]), "+f"(c[3])
        : "r"(a[0]), "r"(a[1]), "r"(a[2]), "r"(a[3]), "r"(b0), "r"(b1));
}

// order-preserving float->u32 with 13-bit index packed into dropped mantissa bits
__device__ __forceinline__ unsigned packscore(float f, int idx) {
    unsigned u = __float_as_uint(f);
    u = ((int)u >= 0) ? (u | 0x80000000u) : ~u;
    return (u & 0xFFFFE000u) | (unsigned)idx;
}
__device__ __forceinline__ float unpackscore(unsigned p) {
    unsigned bits = (p & 0x80000000u) ? (p & 0x7FFFFFFFu) : ~p;
    bits = (bits & 0xFFFFE000u) | 0x1000u;
    return __uint_as_float(bits);
}

#define SQ_LD 260
#define SK_LD 36                 // 128 keys x 32 dims per stage
#define SS_LD 65
#define NSTAGE 512               // 64 chunks x 8 stages (32 dims each)
// floats: 128*260 + 2*128*36 + 128*65 + 128*33 = 55040 -> 220160 B
#define FUSED_SMEM_BYTES (55040 * 4)

__device__ __forceinline__ void issue_stage(
    float* sK, const float* __restrict__ keybase, int tid, int s)
{
    if (s < NSTAGE) {
        const float* gb = keybase + (size_t)((s >> 3) << 7) * KDIM + ((s & 7) << 5);
        float* sb = sK + (s & 1) * (128 * SK_LD);
#pragma unroll
        for (int i = 0; i < 2; i++) {
            int f = tid + i * 512;
            int key = f >> 3, c4 = (f & 7) << 2;
            unsigned saddr = (unsigned)__cvta_generic_to_shared(sb + key * SK_LD + c4);
            const float* ga = gb + (size_t)key * KDIM + c4;
            asm volatile("cp.async.cg.shared.global [%0], [%1], 16;\n"
                         :: "r"(saddr), "l"(ga));
        }
        asm volatile("cp.async.commit_group;\n");
    }
}

__global__ __launch_bounds__(512, 1) void fused_slot(
    const float* __restrict__ keysn, const float* __restrict__ values,
    float* __restrict__ out)
{
    extern __shared__ float smem[];
    float* sQ = smem;
    float* sK = sQ + 128 * SQ_LD;
    unsigned* sS = (unsigned*)(sK + 2 * 128 * SK_LD);
    unsigned* hp = sS + 128 * SS_LD;   // 128 heaps x 33 (packed score|idx)

    const int tid  = threadIdx.x;
    const int lane = tid & 31, wid = tid >> 5;
    const int warp_m = wid >> 2;   // 0..3 -> 32 query rows
    const int warp_n = wid & 3;    // 0..3 -> 32 key cols
    const int g = lane >> 2, tig = lane & 3;
    const int slot = blockIdx.y;
    const int q0 = blockIdx.x * 128;
    const float* keybase = keysn + (size_t)slot * NKEYS * KDIM;

    issue_stage(sK, keybase, tid, 0);

    // q tile (tf32-rounded) — overlaps stage-0 copy
    const float4* qg4 = (const float4*)(g_q + (size_t)q0 * KDIM);
#pragma unroll
    for (int i = 0; i < 16; i++) {
        int f = tid + i * 512;
        int row = f >> 6, c4 = (f & 63) << 2;
        float4 v = qg4[f];
        uint4 u = make_uint4(f2tf32(v.x), f2tf32(v.y), f2tf32(v.z), f2tf32(v.w));
        *(uint4*)&sQ[row * SQ_LD + c4] = u;
    }
    for (int i = tid; i < 128 * 33; i += 512) hp[i] = 0u;   // < any real packed score

    float c[2][4][4];
#pragma unroll
    for (int mm = 0; mm < 2; mm++)
#pragma unroll
        for (int nn = 0; nn < 4; nn++)
#pragma unroll
            for (int r = 0; r < 4; r++) c[mm][nn][r] = 0.f;

    for (int s = 0; s < NSTAGE; s++) {
        asm volatile("cp.async.wait_group 0;\n" ::: "memory");
        __syncthreads();                       // stage s visible; buf (s+1)&1 free
        issue_stage(sK, keybase, tid, s + 1);  // overlaps compute + topk below

        const float* kbuf = sK + (s & 1) * (128 * SK_LD);
        const int kk = (s & 7) << 5;
#pragma unroll
        for (int ks = 0; ks < 4; ks++) {
            unsigned a[2][4];
            const float* qp = sQ + (warp_m * 32) * SQ_LD + kk + ks * 8 + tig;
#pragma unroll
            for (int mm = 0; mm < 2; mm++) {
                const float* qpp = qp + mm * 16 * SQ_LD;
                a[mm][0] = __float_as_uint(qpp[g * SQ_LD]);
                a[mm][1] = __float_as_uint(qpp[(g + 8) * SQ_LD]);
                a[mm][2] = __float_as_uint(qpp[g * SQ_LD + 4]);
                a[mm][3] = __float_as_uint(qpp[(g + 8) * SQ_LD + 4]);
            }
#pragma unroll
            for (int nn = 0; nn < 4; nn++) {
                const float* kp = kbuf + (warp_n * 32 + nn * 8 + g) * SK_LD
                                       + ks * 8 + tig;
                unsigned b0 = __float_as_uint(kp[0]);
                unsigned b1 = __float_as_uint(kp[4]);
#pragma unroll
                for (int mm = 0; mm < 2; mm++) mma_tf32(c[mm][nn], a[mm], b0, b1);
            }
        }

        if ((s & 7) == 7) {                    // 128-key chunk complete
            const int key0 = (s >> 3) << 7;
#pragma unroll
            for (int half = 0; half < 2; half++) {
                if ((warp_n >> 1) == half) {
                    const int cb = (warp_n & 1) * 32;
                    const int ib = key0 + half * 64;
#pragma unroll
                    for (int mm = 0; mm < 2; mm++) {
                        int r0 = warp_m * 32 + mm * 16 + g;
#pragma unroll
                        for (int nn = 0; nn < 4; nn++) {
                            int col = cb + nn * 8 + 2 * tig;
                            sS[r0 * SS_LD + col]           = packscore(c[mm][nn][0], ib + col);
                            sS[r0 * SS_LD + col + 1]       = packscore(c[mm][nn][1], ib + col + 1);
                            sS[(r0 + 8) * SS_LD + col]     = packscore(c[mm][nn][2], ib + col);
                            sS[(r0 + 8) * SS_LD + col + 1] = packscore(c[mm][nn][3], ib + col + 1);
                        }
                    }
                }
                __syncthreads();
                if (tid < 128) {               // one thread per query
                    unsigned* h = hp + tid * 33;
                    const unsigned* srow = sS + tid * SS_LD;
                    unsigned hmin = h[0];
#pragma unroll 4
                    for (int j = 0; j < 64; j++) {
                        unsigned v = srow[j];
                        if (v > hmin) {
                            int p = 0;
                            while (true) {
                                int cl = 2 * p + 1;
                                if (cl >= TOPK) break;
                                int cr = cl + 1;
                                if (cr < TOPK && h[cr] < h[cl]) cl = cr;
                                if (h[cl] >= v) break;
                                h[p] = h[cl]; p = cl;
                            }
                            h[p] = v;
                            hmin = h[0];
                        }
                    }
                }
                if (half == 0) __syncthreads();
            }
#pragma unroll
            for (int mm = 0; mm < 2; mm++)
#pragma unroll
                for (int nn = 0; nn < 4; nn++)
#pragma unroll
                    for (int r = 0; r < 4; r++) c[mm][nn][r] = 0.f;
        }
    }
    __syncthreads();

    // softmax over top-32 + weighted value gather + residual (8 queries/warp)
    const float* vbase = values + (size_t)slot * NKEYS * VDIM;
#pragma unroll
    for (int t = 0; t < 8; t++) {
        const int q = wid * 8 + t;
        const int qg_ = q0 + q;
        unsigned p = hp[q * 33 + lane];
        float s = unpackscore(p);
        int  ki = (int)(p & 0x1FFFu);
        float m = s;
#pragma unroll
        for (int o = 16; o; o >>= 1)
            m = fmaxf(m, __shfl_xor_sync(0xffffffffu, m, o));
        float e = __expf(s - m);
        float sum = e;
#pragma unroll
        for (int o = 16; o; o >>= 1) sum += __shfl_xor_sync(0xffffffffu, sum, o);
        float w = e / sum;

        float4 acc[4];
#pragma unroll
        for (int j = 0; j < 4; j++) acc[j] = make_float4(0.f, 0.f, 0.f, 0.f);
#pragma unroll 4
        for (int k = 0; k < TOPK; k++) {
            float wk = __shfl_sync(0xffffffffu, w, k);
            int   ik = __shfl_sync(0xffffffffu, ki, k);
            const float4* vr = (const float4*)(vbase + (size_t)ik * VDIM);
#pragma unroll
            for (int j = 0; j < 4; j++) {
                float4 v = vr[lane + j * 32];
                acc[j].x += wk * v.x; acc[j].y += wk * v.y;
                acc[j].z += wk * v.z; acc[j].w += wk * v.w;
            }
        }
        const float4* rr = (const float4*)(g_resid + (size_t)qg_ * VDIM);
        float4* op = (float4*)(out + ((size_t)qg_ * NSLOTS + slot) * VDIM);
#pragma unroll
        for (int j = 0; j < 4; j++) {
            float4 r = rr[lane + j * 32];
            op[lane + j * 32] = make_float4(acc[j].x + r.x, acc[j].y + r.y,
                                            acc[j].z + r.z, acc[j].w + r.w);
        }
    }
}

// ---------------------------------------------------------------------------
extern "C" void kernel_launch(void* const* d_in, const int* in_sizes, int n_in,
                              void* d_out, int out_size)
{
    const float* x      = (const float*)d_in[0];
    const float* keys   = (const float*)d_in[1];
    const float* values = (const float*)d_in[2];
    const float* wq     = (const float*)d_in[3];
    const float* bq     = (const float*)d_in[4];
    const float* wr     = (const float*)d_in[5];
    const float* br     = (const float*)d_in[6];
    float* out = (float*)d_out;

    float *qp, *rp, *kp;
    cudaGetSymbolAddress((void**)&qp, g_q);
    cudaGetSymbolAddress((void**)&rp, g_resid);
    cudaGetSymbolAddress((void**)&kp, g_keysn);

    normalize_keys<<<NSLOTS * NKEYS / 8, 256>>>(keys, kp);
    gemm_nt_bias<<<dim3(KDIM / 64, NQ / 64), 128>>>(x, wq, bq, qp, NQ, KDIM, IN_DIM);
    gemm_nt_bias<<<dim3(VDIM / 64, NQ / 64), 128>>>(qp, wr, br, rp, NQ, VDIM, KDIM);

    cudaFuncSetAttribute(fused_slot,
                         cudaFuncAttributeMaxDynamicSharedMemorySize,
                         FUSED_SMEM_BYTES);
    fused_slot<<<dim3(NQ / 128, NSLOTS), 512, FUSED_SMEM_BYTES>>>(kp, values, out);
}